// round 2
// baseline (speedup 1.0000x reference)
#include <cuda_runtime.h>
#include <math.h>

#define BB 4
#define INCH 256
#define NPTS 2048
#define NP1 2049
#define DIM 256
#define KNN 16
#define PHID 64
#define HID 1024
#define NCOL (BB*NP1*KNN)   /* 131136 */
#define NK   (BB*NPTS*KNN)  /* 131072 */
#define EPSV 1e-5f

// ---------------- scratch (static device globals; allocation-free) ----------
__device__ float g_xT[BB*NPTS*INCH];          // x transposed: [b][n][i]
__device__ float g_hx[BB*NP1*DIM];            // [b][n'][c]  (row 0 = cls)
__device__ float g_q [BB*NP1*DIM];
__device__ float g_k [BB*NP1*DIM];
__device__ float g_v [BB*NP1*DIM];
__device__ int   g_idx[BB*NPTS*KNN];
__device__ float g_ph [NK*PHID];              // pos-mlp hidden  [col'][64]
__device__ float g_pe [NK*DIM];               // pe              [col'][256]
__device__ float g_qk [NCOL*DIM];             // qk_all          [col][256]
__device__ float g_hid[NCOL*HID];             // attn hidden     [col][1024]
__device__ float g_lg [NCOL*DIM];             // logits          [col][256]
__device__ float g_agg[BB*NP1*DIM];           // [b][n'][c]
__device__ float g_y  [BB*NP1*DIM];           // [b][n'][c]
__device__ float g_sA[HID], g_tA[HID];        // folded attn bn scale/bias(+b1)
__device__ float g_sP[PHID], g_tP[PHID];      // folded pos  bn scale/bias(+b1)

// ---------------- small prep kernels ---------------------------------------
__global__ void transpose_x_kernel(const float* __restrict__ x){
    __shared__ float tile[32][33];
    int b = blockIdx.z;
    int i0 = blockIdx.y*32, n0 = blockIdx.x*32;
    int tx = threadIdx.x, ty = threadIdx.y;
    tile[ty][tx] = x[(b*INCH + (i0+ty))*NPTS + n0+tx];
    __syncthreads();
    g_xT[(b*NPTS + (n0+ty))*INCH + i0+tx] = tile[tx][ty];
}

__global__ void prep_kernel(const float* __restrict__ ag, const float* __restrict__ abeta,
                            const float* __restrict__ am, const float* __restrict__ av,
                            const float* __restrict__ ab1,
                            const float* __restrict__ pg, const float* __restrict__ pbeta,
                            const float* __restrict__ pm, const float* __restrict__ pv,
                            const float* __restrict__ pb1){
    int t = threadIdx.x;
    if (t < HID){
        float s = ag[t] / sqrtf(av[t] + EPSV);
        g_sA[t] = s;
        g_tA[t] = abeta[t] - am[t]*s + ab1[t]*s;
    }
    if (t < PHID){
        float s = pg[t] / sqrtf(pv[t] + EPSV);
        g_sP[t] = s;
        g_tP[t] = pbeta[t] - pm[t]*s + pb1[t]*s;
    }
}

__global__ void init_cls_kernel(const float* __restrict__ cls){
    g_hx[(blockIdx.x*NP1)*DIM + threadIdx.x] = cls[threadIdx.x];
}

// ---------------- KNN -------------------------------------------------------
__global__ __launch_bounds__(256) void knn_kernel(const float* __restrict__ pos){
    __shared__ float sx[NPTS], sy[NPTS], sz[NPTS];
    int b = blockIdx.y;
    const float* pb = pos + (size_t)b*3*NPTS;
    for (int j = threadIdx.x; j < NPTS; j += 256){
        sx[j] = pb[j]; sy[j] = pb[NPTS+j]; sz[j] = pb[2*NPTS+j];
    }
    __syncthreads();
    int qi = blockIdx.x*256 + threadIdx.x;
    float qx = sx[qi], qy = sy[qi], qz = sz[qi];
    float bd[KNN]; int bi[KNN];
#pragma unroll
    for (int i = 0; i < KNN; i++){ bd[i] = 3.4e38f; bi[i] = 0; }
    float maxv = 3.4e38f; int maxp = 0;
    for (int j = 0; j < NPTS; j++){
        float dx = qx - sx[j], dy = qy - sy[j], dz = qz - sz[j];
        float d = dx*dx + dy*dy + dz*dz;
        if (d < maxv){
            bd[maxp] = d; bi[maxp] = j;
            maxv = bd[0]; maxp = 0;
#pragma unroll
            for (int i = 1; i < KNN; i++)
                if (bd[i] > maxv){ maxv = bd[i]; maxp = i; }
        }
    }
    int base = (b*NPTS + qi)*KNN;
#pragma unroll
    for (int i = 0; i < KNN; i++) g_idx[base+i] = bi[i];
}

// ---------------- pos-MLP hidden (relu(bn(W1p @ pos_rel))) ------------------
__global__ __launch_bounds__(256) void pos_hidden_kernel(const float* __restrict__ pos,
                                                         const float* __restrict__ pw1){
    int b = blockIdx.y, n = blockIdx.x;
    __shared__ float prx[KNN], pry[KNN], prz[KNN];
    int t = threadIdx.x;
    const float* pb = pos + (size_t)b*3*NPTS;
    if (t < KNN){
        int m = g_idx[(b*NPTS+n)*KNN + t];
        prx[t] = pb[n]        - pb[m];
        pry[t] = pb[NPTS+n]   - pb[NPTS+m];
        prz[t] = pb[2*NPTS+n] - pb[2*NPTS+m];
    }
    __syncthreads();
    for (int e = t; e < KNN*PHID; e += 256){
        int k = e >> 6, hh = e & 63;
        float z = pw1[hh*3+0]*prx[k] + pw1[hh*3+1]*pry[k] + pw1[hh*3+2]*prz[k];
        z = z*g_sP[hh] + g_tP[hh];
        g_ph[((b*NPTS+n)*KNN + k)*PHID + hh] = fmaxf(z, 0.f);
    }
}

// ---------------- generic SGEMM: C[M][N] = A[M][K] * Bw[N][K]^T + epi -------
// A row stride = K, Bw row stride = K, C row stride = N.
// EPI==0: C = acc + bias[n] ;  EPI==1: C = relu(acc*scale[n] + bias[n])
template<int EPI>
__global__ __launch_bounds__(256) void gemm_nt(const float* __restrict__ A,
                                               const float* __restrict__ Bw,
                                               float* __restrict__ C,
                                               int M, int N, int Kd,
                                               const float* __restrict__ bias,
                                               const float* __restrict__ scale,
                                               long strideAb, long strideCb){
    A += (long)blockIdx.z * strideAb;
    C += (long)blockIdx.z * strideCb;
    __shared__ __align__(16) float As[16][128];
    __shared__ __align__(16) float Bs[16][128];
    int t = threadIdx.x;
    int m0 = blockIdx.x * 128;
    int n0 = blockIdx.y * 128;
    int tx = t & 15, ty = t >> 4;
    float acc[8][8];
#pragma unroll
    for (int i = 0; i < 8; i++)
#pragma unroll
        for (int j = 0; j < 8; j++) acc[i][j] = 0.f;

    for (int k0 = 0; k0 < Kd; k0 += 16){
#pragma unroll
        for (int l = 0; l < 2; l++){
            int q = t + l*256;
            int r = q >> 2;
            int kc = (q & 3) << 2;
            float4 va = make_float4(0.f,0.f,0.f,0.f);
            if (m0 + r < M) va = *(const float4*)(A + (long)(m0+r)*Kd + k0 + kc);
            As[kc+0][r] = va.x; As[kc+1][r] = va.y; As[kc+2][r] = va.z; As[kc+3][r] = va.w;
            float4 vb = make_float4(0.f,0.f,0.f,0.f);
            if (n0 + r < N) vb = *(const float4*)(Bw + (long)(n0+r)*Kd + k0 + kc);
            Bs[kc+0][r] = vb.x; Bs[kc+1][r] = vb.y; Bs[kc+2][r] = vb.z; Bs[kc+3][r] = vb.w;
        }
        __syncthreads();
#pragma unroll
        for (int kk = 0; kk < 16; kk++){
            float4 a0 = *(const float4*)(&As[kk][ty*8]);
            float4 a1 = *(const float4*)(&As[kk][ty*8+4]);
            float4 b0 = *(const float4*)(&Bs[kk][tx*8]);
            float4 b1 = *(const float4*)(&Bs[kk][tx*8+4]);
            float ar[8] = {a0.x,a0.y,a0.z,a0.w,a1.x,a1.y,a1.z,a1.w};
            float br[8] = {b0.x,b0.y,b0.z,b0.w,b1.x,b1.y,b1.z,b1.w};
#pragma unroll
            for (int i = 0; i < 8; i++)
#pragma unroll
                for (int j = 0; j < 8; j++)
                    acc[i][j] = fmaf(ar[i], br[j], acc[i][j]);
        }
        __syncthreads();
    }
#pragma unroll
    for (int i = 0; i < 8; i++){
        int m = m0 + ty*8 + i;
        if (m < M){
#pragma unroll
            for (int j = 0; j < 8; j++){
                int n = n0 + tx*8 + j;
                float v = acc[i][j];
                if (EPI == 1) v = fmaxf(v*scale[n] + bias[n], 0.f);
                else          v = v + bias[n];
                C[(long)m*N + n] = v;
            }
        }
    }
}

// ---------------- build qk_all [col][c] -------------------------------------
__global__ __launch_bounds__(256) void build_qk_kernel(const float* __restrict__ pos_emb){
    int col = blockIdx.x;          // (b*NP1 + n')*16 + k
    int c   = threadIdx.x;
    int k   = col & 15;
    int nn  = (col >> 4) % NP1;
    int b   = col / (NP1*KNN);
    float val;
    if (nn == 0){
        val = g_q[(b*NP1)*DIM + c] + pos_emb[c];
    } else {
        int n = nn - 1;
        int m = g_idx[(b*NPTS + n)*KNN + k];
        val = g_q[(b*NP1 + nn)*DIM + c]
            - g_k[(b*NP1 + 1 + m)*DIM + c]
            + g_pe[(long)((b*NPTS + n)*KNN + k)*DIM + c];
    }
    g_qk[(long)col*DIM + c] = val;
}

// ---------------- softmax over k + aggregate --------------------------------
__global__ __launch_bounds__(256) void softmax_agg_kernel(const float* __restrict__ pos_emb){
    int b = blockIdx.y, nn = blockIdx.x;    // nn in 0..2048
    int c = threadIdx.x;
    long base = (long)((b*NP1 + nn)*KNN) * DIM;
    float lg[KNN];
#pragma unroll
    for (int k = 0; k < KNN; k++) lg[k] = g_lg[base + (long)k*DIM + c];
    float mx = lg[0];
#pragma unroll
    for (int k = 1; k < KNN; k++) mx = fmaxf(mx, lg[k]);
    float s = 0.f;
#pragma unroll
    for (int k = 0; k < KNN; k++){ lg[k] = expf(lg[k] - mx); s += lg[k]; }
    float inv = 1.f / s;
    float outv;
    if (nn == 0){
        outv = g_v[(b*NP1)*DIM + c] + pos_emb[c];  // softmax of identical cols -> mean = vv
    } else {
        float vn = g_v[(b*NP1 + nn)*DIM + c];
        long peb = (long)((b*NPTS + (nn-1))*KNN) * DIM;
        float acc = 0.f;
#pragma unroll
        for (int k = 0; k < KNN; k++)
            acc += lg[k] * (vn + g_pe[peb + (long)k*DIM + c]);
        outv = acc * inv;
    }
    g_agg[(b*NP1 + nn)*DIM + c] = outv;
}

// ---------------- finalize outputs ------------------------------------------
__global__ void finalize1_kernel(const float* __restrict__ x, float* __restrict__ out){
    int gid = blockIdx.x*256 + threadIdx.x;           // 0 .. B*DIM*NPTS-1
    int n  = gid % NPTS;
    int ch = (gid / NPTS) % DIM;
    int b  = gid / (NPTS*DIM);
    out[gid] = g_y[((b*NP1) + (n+1))*DIM + ch] + x[gid];
}
__global__ void finalize2_kernel(float* __restrict__ out){
    int t = threadIdx.x;                              // 0..1023
    int b = t / DIM, ch = t % DIM;
    out[BB*DIM*NPTS + t] = g_y[(b*NP1)*DIM + ch];
}

// ---------------- launch -----------------------------------------------------
extern "C" void kernel_launch(void* const* d_in, const int* in_sizes, int n_in,
                              void* d_out, int out_size){
    const float* x        = (const float*)d_in[0];
    const float* pos      = (const float*)d_in[1];
    const float* W_start  = (const float*)d_in[2];
    const float* b_start  = (const float*)d_in[3];
    const float* W_key    = (const float*)d_in[4];
    const float* b_key    = (const float*)d_in[5];
    const float* W_query  = (const float*)d_in[6];
    const float* b_query  = (const float*)d_in[7];
    const float* W_value  = (const float*)d_in[8];
    const float* b_value  = (const float*)d_in[9];
    const float* pos_W1   = (const float*)d_in[10];
    const float* pos_b1   = (const float*)d_in[11];
    const float* pos_g    = (const float*)d_in[12];
    const float* pos_beta = (const float*)d_in[13];
    const float* pos_m    = (const float*)d_in[14];
    const float* pos_v    = (const float*)d_in[15];
    const float* pos_W2   = (const float*)d_in[16];
    const float* pos_b2   = (const float*)d_in[17];
    const float* attn_W1  = (const float*)d_in[18];
    const float* attn_b1  = (const float*)d_in[19];
    const float* attn_g   = (const float*)d_in[20];
    const float* attn_beta= (const float*)d_in[21];
    const float* attn_m   = (const float*)d_in[22];
    const float* attn_v   = (const float*)d_in[23];
    const float* attn_W2  = (const float*)d_in[24];
    const float* attn_b2  = (const float*)d_in[25];
    const float* W_end    = (const float*)d_in[26];
    const float* b_end    = (const float*)d_in[27];
    const float* pos_emb  = (const float*)d_in[28];
    const float* cls_tok  = (const float*)d_in[29];
    float* out = (float*)d_out;

    float *pxT, *phx, *pq, *pk, *pv, *pph, *ppe, *pqk, *phid, *plg, *pagg, *py, *psA, *ptA;
    cudaGetSymbolAddress((void**)&pxT,  g_xT);
    cudaGetSymbolAddress((void**)&phx,  g_hx);
    cudaGetSymbolAddress((void**)&pq,   g_q);
    cudaGetSymbolAddress((void**)&pk,   g_k);
    cudaGetSymbolAddress((void**)&pv,   g_v);
    cudaGetSymbolAddress((void**)&pph,  g_ph);
    cudaGetSymbolAddress((void**)&ppe,  g_pe);
    cudaGetSymbolAddress((void**)&pqk,  g_qk);
    cudaGetSymbolAddress((void**)&phid, g_hid);
    cudaGetSymbolAddress((void**)&plg,  g_lg);
    cudaGetSymbolAddress((void**)&pagg, g_agg);
    cudaGetSymbolAddress((void**)&py,   g_y);
    cudaGetSymbolAddress((void**)&psA,  g_sA);
    cudaGetSymbolAddress((void**)&ptA,  g_tA);

    // prep
    transpose_x_kernel<<<dim3(NPTS/32, INCH/32, BB), dim3(32,32)>>>(x);
    prep_kernel<<<1,1024>>>(attn_g, attn_beta, attn_m, attn_v, attn_b1,
                            pos_g, pos_beta, pos_m, pos_v, pos_b1);
    init_cls_kernel<<<BB, DIM>>>(cls_tok);
    knn_kernel<<<dim3(NPTS/256, BB), 256>>>(pos);

    // hx[1:] = W_start @ x + b   (per batch)
    gemm_nt<0><<<dim3(NPTS/128, DIM/128, BB), 256>>>(
        pxT, W_start, phx + DIM, NPTS, DIM, INCH, b_start, nullptr,
        (long)NPTS*INCH, (long)NP1*DIM);

    // q,k,v = W @ hx + b
    gemm_nt<0><<<dim3((NP1+127)/128, DIM/128, BB), 256>>>(
        phx, W_query, pq, NP1, DIM, DIM, b_query, nullptr, (long)NP1*DIM, (long)NP1*DIM);
    gemm_nt<0><<<dim3((NP1+127)/128, DIM/128, BB), 256>>>(
        phx, W_key,   pk, NP1, DIM, DIM, b_key,   nullptr, (long)NP1*DIM, (long)NP1*DIM);
    gemm_nt<0><<<dim3((NP1+127)/128, DIM/128, BB), 256>>>(
        phx, W_value, pv, NP1, DIM, DIM, b_value, nullptr, (long)NP1*DIM, (long)NP1*DIM);

    // pos-MLP
    pos_hidden_kernel<<<dim3(NPTS, BB), 256>>>(pos, pos_W1);
    gemm_nt<0><<<dim3(NK/128, DIM/128, 1), 256>>>(
        pph, pos_W2, ppe, NK, DIM, PHID, pos_b2, nullptr, 0, 0);

    // qk_all
    build_qk_kernel<<<NCOL, 256>>>(pos_emb);

    // attn MLP (dominant)
    gemm_nt<1><<<dim3((NCOL+127)/128, HID/128, 1), 256>>>(
        pqk, attn_W1, phid, NCOL, HID, DIM, ptA, psA, 0, 0);
    gemm_nt<0><<<dim3((NCOL+127)/128, DIM/128, 1), 256>>>(
        phid, attn_W2, plg, NCOL, DIM, HID, attn_b2, nullptr, 0, 0);

    // softmax + aggregate
    softmax_agg_kernel<<<dim3(NP1, BB), 256>>>(pos_emb);

    // y = W_end @ agg + b
    gemm_nt<0><<<dim3((NP1+127)/128, DIM/128, BB), 256>>>(
        pagg, W_end, py, NP1, DIM, DIM, b_end, nullptr, (long)NP1*DIM, (long)NP1*DIM);

    // outputs
    finalize1_kernel<<<(BB*DIM*NPTS)/256, 256>>>(x, out);
    finalize2_kernel<<<1, BB*DIM>>>(out);
}

// round 3
// speedup vs baseline: 2.3848x; 2.3848x over previous
#include <cuda_runtime.h>
#include <math.h>
#include <stdint.h>

#define BB 4
#define INCH 256
#define NPTS 2048
#define NP1 2049
#define DIM 256
#define KNN 16
#define PHID 64
#define HID 1024
#define NCOL (BB*NP1*KNN)   /* 131136 */
#define NK   (BB*NPTS*KNN)  /* 131072 */
#define NCH  8              /* knn candidate chunks */
#define EPSV 1e-5f

// ---------------- scratch (static device globals; allocation-free) ----------
__device__ float g_xT[BB*NPTS*INCH];
__device__ float g_hx[BB*NP1*DIM];
__device__ float g_q [BB*NP1*DIM];
__device__ float g_k [BB*NP1*DIM];
__device__ float g_v [BB*NP1*DIM];
__device__ int   g_idx[BB*NPTS*KNN];
__device__ float g_pd[BB*NPTS*NCH*KNN];
__device__ int   g_pi[BB*NPTS*NCH*KNN];
__device__ float g_ph [NK*PHID];
__device__ float g_pe [NK*DIM];
__device__ float g_hid[(long)NCOL*HID];
__device__ float g_lg [NCOL*DIM];
__device__ float g_agg[BB*NP1*DIM];
__device__ float g_y  [BB*NP1*DIM];
__device__ float g_w1q[BB*NP1*HID];
__device__ float g_w1k[BB*NPTS*HID];
__device__ float g_Wc [HID*PHID];
__device__ float g_sA[HID], g_tA[HID], g_w1pb[HID];
__device__ float g_sP[PHID], g_tP[PHID];

// ---------------- helpers ----------------------------------------------------
__device__ __forceinline__ uint32_t f2tf32(float x){
    uint32_t r; asm("cvt.rna.tf32.f32 %0, %1;" : "=r"(r) : "f"(x)); return r;
}
__device__ __forceinline__ void mma_tf32(float&c0,float&c1,float&c2,float&c3,
   uint32_t a0,uint32_t a1,uint32_t a2,uint32_t a3,uint32_t b0,uint32_t b1){
  asm volatile("mma.sync.aligned.m16n8k8.row.col.f32.tf32.tf32.f32 "
    "{%0,%1,%2,%3}, {%4,%5,%6,%7}, {%8,%9}, {%0,%1,%2,%3};\n"
    : "+f"(c0),"+f"(c1),"+f"(c2),"+f"(c3)
    : "r"(a0),"r"(a1),"r"(a2),"r"(a3),"r"(b0),"r"(b1));
}

// ---------------- small prep kernels ---------------------------------------
__global__ void transpose_x_kernel(const float* __restrict__ x){
    __shared__ float tile[32][33];
    int b = blockIdx.z;
    int i0 = blockIdx.y*32, n0 = blockIdx.x*32;
    int tx = threadIdx.x, ty = threadIdx.y;
    tile[ty][tx] = x[(b*INCH + (i0+ty))*NPTS + n0+tx];
    __syncthreads();
    g_xT[(b*NPTS + (n0+ty))*INCH + i0+tx] = tile[tx][ty];
}

__global__ void prep_kernel(const float* __restrict__ ag, const float* __restrict__ abeta,
                            const float* __restrict__ am, const float* __restrict__ av,
                            const float* __restrict__ ab1,
                            const float* __restrict__ pg, const float* __restrict__ pbeta,
                            const float* __restrict__ pm, const float* __restrict__ pv,
                            const float* __restrict__ pb1,
                            const float* __restrict__ W1, const float* __restrict__ pb2){
    int t = threadIdx.x;
    if (t < HID){
        float s = ag[t] / sqrtf(av[t] + EPSV);
        g_sA[t] = s;
        g_tA[t] = abeta[t] - am[t]*s + ab1[t]*s;
        float acc = 0.f;
        for (int c = 0; c < DIM; c++) acc += W1[t*DIM+c]*pb2[c];
        g_w1pb[t] = acc;
    }
    if (t < PHID){
        float s = pg[t] / sqrtf(pv[t] + EPSV);
        g_sP[t] = s;
        g_tP[t] = pbeta[t] - pm[t]*s + pb1[t]*s;
    }
}

// Wc[h][p] = sum_c W1[h][c] * W2p[c][p]
__global__ void wc_kernel(const float* __restrict__ W1, const float* __restrict__ W2p){
    int h = blockIdx.x, p = threadIdx.x;   // 1024 blocks, 64 threads
    float s = 0.f;
    for (int c = 0; c < DIM; c++) s += W1[h*DIM+c]*W2p[c*PHID+p];
    g_Wc[h*PHID+p] = s;
}

__global__ void init_cls_kernel(const float* __restrict__ cls){
    g_hx[(blockIdx.x*NP1)*DIM + threadIdx.x] = cls[threadIdx.x];
}

// q0 += pos_emb ; v0 += pos_emb
__global__ void addpos_kernel(const float* __restrict__ pos_emb){
    int b = blockIdx.x, c = threadIdx.x;
    g_q[(b*NP1)*DIM + c] += pos_emb[c];
    g_v[(b*NP1)*DIM + c] += pos_emb[c];
}

// ---------------- KNN (chunked) ---------------------------------------------
__global__ __launch_bounds__(256) void knn_part_kernel(const float* __restrict__ pos){
    __shared__ float sx[256], sy[256], sz[256];
    int b = blockIdx.y, ch = blockIdx.z;
    const float* pb = pos + (size_t)b*3*NPTS;
    int j0 = ch*256;
    int t = threadIdx.x;
    sx[t] = pb[j0+t]; sy[t] = pb[NPTS+j0+t]; sz[t] = pb[2*NPTS+j0+t];
    __syncthreads();
    int qi = blockIdx.x*256 + t;
    float qx = pb[qi], qy = pb[NPTS+qi], qz = pb[2*NPTS+qi];
    float bd[KNN]; int bi[KNN];
#pragma unroll
    for (int i = 0; i < KNN; i++){ bd[i] = 3.4e38f; bi[i] = 0; }
    float maxv = 3.4e38f; int maxp = 0;
    for (int j = 0; j < 256; j++){
        float dx = qx - sx[j], dy = qy - sy[j], dz = qz - sz[j];
        float d = dx*dx + dy*dy + dz*dz;
        if (d < maxv){
            bd[maxp] = d; bi[maxp] = j0 + j;
            maxv = bd[0]; maxp = 0;
#pragma unroll
            for (int i = 1; i < KNN; i++)
                if (bd[i] > maxv){ maxv = bd[i]; maxp = i; }
        }
    }
    long base = ((long)(b*NPTS + qi)*NCH + ch)*KNN;
#pragma unroll
    for (int i = 0; i < KNN; i++){ g_pd[base+i] = bd[i]; g_pi[base+i] = bi[i]; }
}

__global__ __launch_bounds__(256) void knn_merge_kernel(){
    int b = blockIdx.y;
    int qi = blockIdx.x*256 + threadIdx.x;
    long base = (long)(b*NPTS + qi)*NCH*KNN;
    float bd[KNN]; int bi[KNN];
#pragma unroll
    for (int i = 0; i < KNN; i++){ bd[i] = 3.4e38f; bi[i] = 0; }
    float maxv = 3.4e38f; int maxp = 0;
    for (int j = 0; j < NCH*KNN; j++){
        float d = g_pd[base+j];
        if (d < maxv){
            bd[maxp] = d; bi[maxp] = g_pi[base+j];
            maxv = bd[0]; maxp = 0;
#pragma unroll
            for (int i = 1; i < KNN; i++)
                if (bd[i] > maxv){ maxv = bd[i]; maxp = i; }
        }
    }
    int ob = (b*NPTS + qi)*KNN;
#pragma unroll
    for (int i = 0; i < KNN; i++) g_idx[ob+i] = bi[i];
}

// ---------------- pos-MLP hidden (relu(bn(W1p @ pos_rel))) ------------------
__global__ __launch_bounds__(256) void pos_hidden_kernel(const float* __restrict__ pos,
                                                         const float* __restrict__ pw1){
    int b = blockIdx.y, n = blockIdx.x;
    __shared__ float prx[KNN], pry[KNN], prz[KNN];
    int t = threadIdx.x;
    const float* pb = pos + (size_t)b*3*NPTS;
    if (t < KNN){
        int m = g_idx[(b*NPTS+n)*KNN + t];
        prx[t] = pb[n]        - pb[m];
        pry[t] = pb[NPTS+n]   - pb[NPTS+m];
        prz[t] = pb[2*NPTS+n] - pb[2*NPTS+m];
    }
    __syncthreads();
    for (int e = t; e < KNN*PHID; e += 256){
        int k = e >> 6, hh = e & 63;
        float z = pw1[hh*3+0]*prx[k] + pw1[hh*3+1]*pry[k] + pw1[hh*3+2]*prz[k];
        z = z*g_sP[hh] + g_tP[hh];
        g_ph[((b*NPTS+n)*KNN + k)*PHID + hh] = fmaxf(z, 0.f);
    }
}

// ---------------- tf32 tensor-core GEMM: C[M][N] = A[M][K]*Bw[N][K]^T --------
// EPI 0: C = acc + bias[n]
// EPI 2: folded attn-hidden epilogue (gathers w1q/w1k, bn+relu, scatter to g_hid)
// EPI 3: C = acc
#define GEMM_LOAD(k0_) do{ \
  _Pragma("unroll") \
  for (int l=0;l<2;l++){ \
    int q_ = t + l*256; \
    int row_ = q_ >> 2; \
    int kc0_ = (q_ & 3) << 2; \
    pa[l] = (m0+row_ < M) ? *(const float4*)(A + (long)(m0+row_)*K + (k0_) + kc0_) \
                          : make_float4(0.f,0.f,0.f,0.f); \
    pb_[l] = *(const float4*)(Bw + (long)(n0+row_)*K + (k0_) + kc0_); \
  } }while(0)

#define GEMM_STAGE(buf_) do{ \
  _Pragma("unroll") \
  for (int l=0;l<2;l++){ \
    int q_ = t + l*256; \
    int row_ = q_ >> 2; \
    int kc0_ = (q_ & 3) << 2; \
    float va_[4] = {pa[l].x, pa[l].y, pa[l].z, pa[l].w}; \
    float vb_[4] = {pb_[l].x, pb_[l].y, pb_[l].z, pb_[l].w}; \
    int mt_ = row_ >> 4, r_ = row_ & 15; \
    int nt_ = row_ >> 3, nv_ = row_ & 7; \
    _Pragma("unroll") \
    for (int e=0;e<4;e++){ \
      int kc_ = kc0_ + e, k8_ = kc_ >> 3, kin_ = kc_ & 7; \
      As[buf_][(((k8_<<3)+mt_)*32 + ((r_&7)<<2) + (kin_&3))*4 + (r_>>3) + ((kin_>>2)<<1)] = f2tf32(va_[e]); \
      Bs[buf_][(((k8_<<4)+nt_)*32 + (nv_<<2) + (kin_&3))*2 + (kin_>>2)] = f2tf32(vb_[e]); \
    } } }while(0)

template<int EPI>
__global__ __launch_bounds__(256,2) void gemm_tc(const float* __restrict__ A,
        const float* __restrict__ Bw, float* __restrict__ C,
        int M, int N, int K, const float* __restrict__ bias,
        long strideAb, long strideCb){
    A += (long)blockIdx.z * strideAb;
    C += (long)blockIdx.z * strideCb;
    __shared__ __align__(16) uint32_t As[2][2048];
    __shared__ __align__(16) uint32_t Bs[2][2048];
    const int t = threadIdx.x, lane = t & 31, w = t >> 5;
    const int wm = w >> 2, wn = w & 3;
    const int m0 = blockIdx.x*128, n0 = blockIdx.y*128;
    float acc[4][4][4];
#pragma unroll
    for (int i=0;i<4;i++)
#pragma unroll
      for (int j=0;j<4;j++)
#pragma unroll
        for (int c=0;c<4;c++) acc[i][j][c] = 0.f;
    float4 pa[2], pb_[2];

    GEMM_LOAD(0);
    GEMM_STAGE(0);
    __syncthreads();
    const int nIter = K >> 4;
    for (int it = 0; it < nIter; ++it){
        int buf = it & 1;
        if (it+1 < nIter) GEMM_LOAD((it+1)<<4);
#pragma unroll
        for (int k8=0;k8<2;k8++){
            uint4 af[4]; uint2 bf[4];
#pragma unroll
            for (int i=0;i<4;i++)
                af[i] = *(const uint4*)&As[buf][(((k8<<3) + (wm<<2) + i)*32 + lane)*4];
#pragma unroll
            for (int j=0;j<4;j++)
                bf[j] = *(const uint2*)&Bs[buf][(((k8<<4) + (wn<<2) + j)*32 + lane)*2];
#pragma unroll
            for (int i=0;i<4;i++)
#pragma unroll
                for (int j=0;j<4;j++)
                    mma_tf32(acc[i][j][0],acc[i][j][1],acc[i][j][2],acc[i][j][3],
                             af[i].x,af[i].y,af[i].z,af[i].w, bf[j].x,bf[j].y);
        }
        if (it+1 < nIter) GEMM_STAGE(buf^1);
        __syncthreads();
    }

    const int r0 = lane >> 2, cq = (lane & 3) << 1;
#pragma unroll
    for (int i=0;i<4;i++){
#pragma unroll
        for (int half=0; half<2; half++){
            int m = m0 + wm*64 + i*16 + r0 + half*8;
            if (m >= M) continue;
            if (EPI == 2){
                int b  = m >> 15;
                int n  = (m >> 4) & (NPTS-1);
                int kk = m & 15;
                int midx = g_idx[((b*NPTS)+n)*KNN + kk];
                const float* wq = g_w1q + (long)(b*NP1 + n + 1)*HID;
                const float* wk = g_w1k + (long)(b*NPTS + midx)*HID;
                float* dst = g_hid + (long)((b*NP1 + n + 1)*KNN + kk)*HID;
#pragma unroll
                for (int j=0;j<4;j++){
                    int h = n0 + wn*32 + j*8 + cq;
                    float2 q2 = *(const float2*)&wq[h];
                    float2 k2 = *(const float2*)&wk[h];
                    float2 p2 = *(const float2*)&g_w1pb[h];
                    float2 s2 = *(const float2*)&g_sA[h];
                    float2 t2 = *(const float2*)&g_tA[h];
                    float2 o;
                    o.x = fmaxf((acc[i][j][half*2+0] + q2.x - k2.x + p2.x)*s2.x + t2.x, 0.f);
                    o.y = fmaxf((acc[i][j][half*2+1] + q2.y - k2.y + p2.y)*s2.y + t2.y, 0.f);
                    *(float2*)&dst[h] = o;
                }
            } else {
                float* crow = C + (long)m*N;
#pragma unroll
                for (int j=0;j<4;j++){
                    int n = n0 + wn*32 + j*8 + cq;
                    float2 o;
                    if (EPI == 0){
                        float2 bv = *(const float2*)&bias[n];
                        o.x = acc[i][j][half*2+0] + bv.x;
                        o.y = acc[i][j][half*2+1] + bv.y;
                    } else {
                        o.x = acc[i][j][half*2+0];
                        o.y = acc[i][j][half*2+1];
                    }
                    *(float2*)&crow[n] = o;
                }
            }
        }
    }
}

// ---------------- cls hidden -------------------------------------------------
__global__ void cls_hidden_kernel(){
    int b = blockIdx.x >> 4, kk = blockIdx.x & 15;
    long col = (long)(b*NP1)*KNN + kk;
    for (int h = threadIdx.x; h < HID; h += 256){
        float v = fmaxf(g_w1q[(long)(b*NP1)*HID + h]*g_sA[h] + g_tA[h], 0.f);
        g_hid[col*HID + h] = v;
    }
}

// ---------------- softmax over k + aggregate --------------------------------
__global__ __launch_bounds__(256) void softmax_agg_kernel(){
    int b = blockIdx.y, nn = blockIdx.x;    // nn in 0..2048
    int c = threadIdx.x;
    float outv;
    if (nn == 0){
        outv = g_v[(b*NP1)*DIM + c];        // v0 already includes pos_emb
    } else {
        long base = (long)((b*NP1 + nn)*KNN) * DIM;
        float lg[KNN];
#pragma unroll
        for (int k = 0; k < KNN; k++) lg[k] = g_lg[base + (long)k*DIM + c];
        float mx = lg[0];
#pragma unroll
        for (int k = 1; k < KNN; k++) mx = fmaxf(mx, lg[k]);
        float s = 0.f;
#pragma unroll
        for (int k = 0; k < KNN; k++){ lg[k] = expf(lg[k] - mx); s += lg[k]; }
        float inv = 1.f / s;
        float vn = g_v[(b*NP1 + nn)*DIM + c];
        long peb = (long)((b*NPTS + (nn-1))*KNN) * DIM;
        float acc = 0.f;
#pragma unroll
        for (int k = 0; k < KNN; k++)
            acc += lg[k] * (vn + g_pe[peb + (long)k*DIM + c]);
        outv = acc * inv;
    }
    g_agg[(b*NP1 + nn)*DIM + c] = outv;
}

// ---------------- finalize outputs ------------------------------------------
__global__ void finalize1_kernel(const float* __restrict__ x, float* __restrict__ out){
    int gid = blockIdx.x*256 + threadIdx.x;
    int n  = gid % NPTS;
    int ch = (gid / NPTS) % DIM;
    int b  = gid / (NPTS*DIM);
    out[gid] = g_y[((b*NP1) + (n+1))*DIM + ch] + x[gid];
}
__global__ void finalize2_kernel(float* __restrict__ out){
    int t = threadIdx.x;
    int b = t / DIM, ch = t % DIM;
    out[BB*DIM*NPTS + t] = g_y[(b*NP1)*DIM + ch];
}

// ---------------- launch -----------------------------------------------------
extern "C" void kernel_launch(void* const* d_in, const int* in_sizes, int n_in,
                              void* d_out, int out_size){
    const float* x        = (const float*)d_in[0];
    const float* pos      = (const float*)d_in[1];
    const float* W_start  = (const float*)d_in[2];
    const float* b_start  = (const float*)d_in[3];
    const float* W_key    = (const float*)d_in[4];
    const float* b_key    = (const float*)d_in[5];
    const float* W_query  = (const float*)d_in[6];
    const float* b_query  = (const float*)d_in[7];
    const float* W_value  = (const float*)d_in[8];
    const float* b_value  = (const float*)d_in[9];
    const float* pos_W1   = (const float*)d_in[10];
    const float* pos_b1   = (const float*)d_in[11];
    const float* pos_g    = (const float*)d_in[12];
    const float* pos_beta = (const float*)d_in[13];
    const float* pos_m    = (const float*)d_in[14];
    const float* pos_v    = (const float*)d_in[15];
    const float* pos_W2   = (const float*)d_in[16];
    const float* pos_b2   = (const float*)d_in[17];
    const float* attn_W1  = (const float*)d_in[18];
    const float* attn_b1  = (const float*)d_in[19];
    const float* attn_g   = (const float*)d_in[20];
    const float* attn_beta= (const float*)d_in[21];
    const float* attn_m   = (const float*)d_in[22];
    const float* attn_v   = (const float*)d_in[23];
    const float* attn_W2  = (const float*)d_in[24];
    const float* attn_b2  = (const float*)d_in[25];
    const float* W_end    = (const float*)d_in[26];
    const float* b_end    = (const float*)d_in[27];
    const float* pos_emb  = (const float*)d_in[28];
    const float* cls_tok  = (const float*)d_in[29];
    float* out = (float*)d_out;

    float *pxT, *phx, *pq, *pk, *pv, *pph, *ppe, *phid, *plg, *pagg, *py, *pw1q, *pw1k, *pWc;
    cudaGetSymbolAddress((void**)&pxT,  g_xT);
    cudaGetSymbolAddress((void**)&phx,  g_hx);
    cudaGetSymbolAddress((void**)&pq,   g_q);
    cudaGetSymbolAddress((void**)&pk,   g_k);
    cudaGetSymbolAddress((void**)&pv,   g_v);
    cudaGetSymbolAddress((void**)&pph,  g_ph);
    cudaGetSymbolAddress((void**)&ppe,  g_pe);
    cudaGetSymbolAddress((void**)&phid, g_hid);
    cudaGetSymbolAddress((void**)&plg,  g_lg);
    cudaGetSymbolAddress((void**)&pagg, g_agg);
    cudaGetSymbolAddress((void**)&py,   g_y);
    cudaGetSymbolAddress((void**)&pw1q, g_w1q);
    cudaGetSymbolAddress((void**)&pw1k, g_w1k);
    cudaGetSymbolAddress((void**)&pWc,  g_Wc);

    // prep
    transpose_x_kernel<<<dim3(NPTS/32, INCH/32, BB), dim3(32,32)>>>(x);
    prep_kernel<<<1,1024>>>(attn_g, attn_beta, attn_m, attn_v, attn_b1,
                            pos_g, pos_beta, pos_m, pos_v, pos_b1,
                            attn_W1, pos_b2);
    wc_kernel<<<HID, PHID>>>(attn_W1, pos_W2);
    init_cls_kernel<<<BB, DIM>>>(cls_tok);
    knn_part_kernel<<<dim3(NPTS/256, BB, NCH), 256>>>(pos);
    knn_merge_kernel<<<dim3(NPTS/256, BB), 256>>>();

    // hx[1:] = W_start @ x + b (per batch)
    gemm_tc<0><<<dim3(NPTS/128, DIM/128, BB), 256>>>(
        pxT, W_start, phx + DIM, NPTS, DIM, INCH, b_start,
        (long)NPTS*INCH, (long)NP1*DIM);

    // q,k,v  (hx is contiguous across batches: M = B*NP1)
    gemm_tc<0><<<dim3((BB*NP1+127)/128, DIM/128, 1), 256>>>(
        phx, W_query, pq, BB*NP1, DIM, DIM, b_query, 0, 0);
    gemm_tc<0><<<dim3((BB*NP1+127)/128, DIM/128, 1), 256>>>(
        phx, W_key,   pk, BB*NP1, DIM, DIM, b_key,   0, 0);
    gemm_tc<0><<<dim3((BB*NP1+127)/128, DIM/128, 1), 256>>>(
        phx, W_value, pv, BB*NP1, DIM, DIM, b_value, 0, 0);

    addpos_kernel<<<BB, DIM>>>(pos_emb);

    // W1@q (incl. cls row with pos_emb), W1@k (rows 1..2048 per batch)
    gemm_tc<3><<<dim3((BB*NP1+127)/128, HID/128, 1), 256>>>(
        pq, attn_W1, pw1q, BB*NP1, HID, DIM, nullptr, 0, 0);
    gemm_tc<3><<<dim3(NPTS/128, HID/128, BB), 256>>>(
        pk + DIM, attn_W1, pw1k, NPTS, HID, DIM, nullptr,
        (long)NP1*DIM, (long)NPTS*HID);

    // pos-MLP
    pos_hidden_kernel<<<dim3(NPTS, BB), 256>>>(pos, pos_W1);
    gemm_tc<0><<<dim3(NK/128, DIM/128, 1), 256>>>(
        pph, pos_W2, ppe, NK, DIM, PHID, pos_b2, 0, 0);

    // folded attn hidden:  hid = relu((Wc@ph + w1q - w1k + w1pb)*sA + tA)
    gemm_tc<2><<<dim3(NK/128, HID/128, 1), 256>>>(
        pph, pWc, nullptr, NK, HID, PHID, nullptr, 0, 0);
    cls_hidden_kernel<<<BB*KNN, 256>>>();

    // logits = W2 @ hid + b2
    gemm_tc<0><<<dim3((NCOL+127)/128, DIM/128, 1), 256>>>(
        phid, attn_W2, plg, NCOL, DIM, HID, attn_b2, 0, 0);

    // softmax + aggregate
    softmax_agg_kernel<<<dim3(NP1, BB), 256>>>();

    // y = W_end @ agg + b
    gemm_tc<0><<<dim3((BB*NP1+127)/128, DIM/128, 1), 256>>>(
        pagg, W_end, py, BB*NP1, DIM, DIM, b_end, 0, 0);

    // outputs
    finalize1_kernel<<<(BB*DIM*NPTS)/256, 256>>>(x, out);
    finalize2_kernel<<<1, BB*DIM>>>(out);
}

// round 5
// speedup vs baseline: 2.8421x; 1.1917x over previous
#include <cuda_runtime.h>
#include <math.h>
#include <stdint.h>

#define BB 4
#define INCH 256
#define NPTS 2048
#define NP1 2049
#define DIM 256
#define KNN 16
#define PHID 64
#define HID 1024
#define NCOL (BB*NP1*KNN)   /* 131136 */
#define NK   (BB*NPTS*KNN)  /* 131072 */
#define NCH  8
#define EPSV 1e-5f
#define GSMEM 61440         /* 3 stages * (2560+2560) floats * 4B */

// ---------------- scratch ----------------------------------------------------
__device__ float g_xT[BB*NPTS*INCH];
__device__ float g_hx[BB*NP1*DIM];
__device__ float g_q [BB*NP1*DIM];
__device__ float g_k [BB*NP1*DIM];
__device__ float g_v [BB*NP1*DIM];
__device__ int   g_idx[BB*NPTS*KNN];
__device__ float g_pd[BB*NPTS*NCH*KNN];
__device__ int   g_pi[BB*NPTS*NCH*KNN];
__device__ float g_ph [NK*PHID];
__device__ float g_pe [(long)NK*DIM];
__device__ float g_hid[(long)NCOL*HID];
__device__ float g_agg[BB*NP1*DIM];
__device__ float g_y  [BB*NP1*DIM];
__device__ float g_w1q[BB*NP1*HID];
__device__ float g_w1k[BB*NPTS*HID];
__device__ float g_Wc [HID*PHID];
__device__ float g_sA[HID], g_tA[HID], g_w1pb[HID];
__device__ float g_sP[PHID], g_tP[PHID];
// rounded weights
__device__ float g_rWs[DIM*INCH];
__device__ float g_rWq[DIM*DIM];
__device__ float g_rWk[DIM*DIM];
__device__ float g_rWv[DIM*DIM];
__device__ float g_rW1[HID*DIM];
__device__ float g_rP2[DIM*PHID];
__device__ float g_rW2[DIM*HID];
__device__ float g_rWe[INCH*DIM];

// ---------------- helpers ----------------------------------------------------
__device__ __forceinline__ float rtf(float x){
    uint32_t r; asm("cvt.rna.tf32.f32 %0, %1;" : "=r"(r) : "f"(x));
    return __uint_as_float(r);
}
__device__ __forceinline__ void mma_tf32(float&c0,float&c1,float&c2,float&c3,
   uint32_t a0,uint32_t a1,uint32_t a2,uint32_t a3,uint32_t b0,uint32_t b1){
  asm volatile("mma.sync.aligned.m16n8k8.row.col.f32.tf32.tf32.f32 "
    "{%0,%1,%2,%3}, {%4,%5,%6,%7}, {%8,%9}, {%0,%1,%2,%3};\n"
    : "+f"(c0),"+f"(c1),"+f"(c2),"+f"(c3)
    : "r"(a0),"r"(a1),"r"(a2),"r"(a3),"r"(b0),"r"(b1));
}
__device__ __forceinline__ void cp16(uint32_t dst, const void* src){
    asm volatile("cp.async.cg.shared.global [%0], [%1], 16;" :: "r"(dst), "l"(src));
}
__device__ __forceinline__ void cpcommit(){ asm volatile("cp.async.commit_group;"); }
__device__ __forceinline__ void cpwait1(){ asm volatile("cp.async.wait_group 1;"); }

// ---------------- small prep kernels ----------------------------------------
__global__ void roundcpy_kernel(const float* __restrict__ src, float* __restrict__ dst){
    int i = blockIdx.x*256 + threadIdx.x;
    dst[i] = rtf(src[i]);
}

__global__ void transpose_x_kernel(const float* __restrict__ x){
    __shared__ float tile[32][33];
    int b = blockIdx.z;
    int i0 = blockIdx.y*32, n0 = blockIdx.x*32;
    int tx = threadIdx.x, ty = threadIdx.y;
    tile[ty][tx] = x[(b*INCH + (i0+ty))*NPTS + n0+tx];
    __syncthreads();
    g_xT[(b*NPTS + (n0+ty))*INCH + i0+tx] = rtf(tile[tx][ty]);
}

__global__ void prep_kernel(const float* __restrict__ ag, const float* __restrict__ abeta,
                            const float* __restrict__ am, const float* __restrict__ av,
                            const float* __restrict__ ab1,
                            const float* __restrict__ pg, const float* __restrict__ pbeta,
                            const float* __restrict__ pm, const float* __restrict__ pv,
                            const float* __restrict__ pb1,
                            const float* __restrict__ W1, const float* __restrict__ pb2){
    int t = threadIdx.x;
    if (t < HID){
        float s = ag[t] / sqrtf(av[t] + EPSV);
        g_sA[t] = s;
        g_tA[t] = abeta[t] - am[t]*s + ab1[t]*s;
        float acc = 0.f;
        for (int c = 0; c < DIM; c++) acc += W1[t*DIM+c]*pb2[c];
        g_w1pb[t] = acc;
    }
    if (t < PHID){
        float s = pg[t] / sqrtf(pv[t] + EPSV);
        g_sP[t] = s;
        g_tP[t] = pbeta[t] - pm[t]*s + pb1[t]*s;
    }
}

__global__ void wc_kernel(const float* __restrict__ W1, const float* __restrict__ W2p){
    int h = blockIdx.x, p = threadIdx.x;
    float s = 0.f;
    for (int c = 0; c < DIM; c++) s += W1[h*DIM+c]*W2p[c*PHID+p];
    g_Wc[h*PHID+p] = rtf(s);
}

__global__ void init_cls_kernel(const float* __restrict__ cls){
    g_hx[(blockIdx.x*NP1)*DIM + threadIdx.x] = rtf(cls[threadIdx.x]);
}

__global__ void addpos_kernel(const float* __restrict__ pos_emb){
    int b = blockIdx.x, c = threadIdx.x;
    g_q[(b*NP1)*DIM + c] = rtf(g_q[(b*NP1)*DIM + c] + pos_emb[c]);
    g_v[(b*NP1)*DIM + c] += pos_emb[c];
}

// ---------------- KNN (chunked) ---------------------------------------------
__global__ __launch_bounds__(256) void knn_part_kernel(const float* __restrict__ pos){
    __shared__ float sx[256], sy[256], sz[256];
    int b = blockIdx.y, ch = blockIdx.z;
    const float* pb = pos + (size_t)b*3*NPTS;
    int j0 = ch*256;
    int t = threadIdx.x;
    sx[t] = pb[j0+t]; sy[t] = pb[NPTS+j0+t]; sz[t] = pb[2*NPTS+j0+t];
    __syncthreads();
    int qi = blockIdx.x*256 + t;
    float qx = pb[qi], qy = pb[NPTS+qi], qz = pb[2*NPTS+qi];
    float bd[KNN]; int bi[KNN];
#pragma unroll
    for (int i = 0; i < KNN; i++){ bd[i] = 3.4e38f; bi[i] = 0; }
    float maxv = 3.4e38f; int maxp = 0;
    for (int j = 0; j < 256; j++){
        float dx = qx - sx[j], dy = qy - sy[j], dz = qz - sz[j];
        float d = dx*dx + dy*dy + dz*dz;
        if (d < maxv){
            bd[maxp] = d; bi[maxp] = j0 + j;
            maxv = bd[0]; maxp = 0;
#pragma unroll
            for (int i = 1; i < KNN; i++)
                if (bd[i] > maxv){ maxv = bd[i]; maxp = i; }
        }
    }
    long base = ((long)(b*NPTS + qi)*NCH + ch)*KNN;
#pragma unroll
    for (int i = 0; i < KNN; i++){ g_pd[base+i] = bd[i]; g_pi[base+i] = bi[i]; }
}

__global__ __launch_bounds__(256) void knn_merge_kernel(){
    int b = blockIdx.y;
    int qi = blockIdx.x*256 + threadIdx.x;
    long base = (long)(b*NPTS + qi)*NCH*KNN;
    float bd[KNN]; int bi[KNN];
#pragma unroll
    for (int i = 0; i < KNN; i++){ bd[i] = 3.4e38f; bi[i] = 0; }
    float maxv = 3.4e38f; int maxp = 0;
    for (int j = 0; j < NCH*KNN; j++){
        float d = g_pd[base+j];
        if (d < maxv){
            bd[maxp] = d; bi[maxp] = g_pi[base+j];
            maxv = bd[0]; maxp = 0;
#pragma unroll
            for (int i = 1; i < KNN; i++)
                if (bd[i] > maxv){ maxv = bd[i]; maxp = i; }
        }
    }
    int ob = (b*NPTS + qi)*KNN;
#pragma unroll
    for (int i = 0; i < KNN; i++) g_idx[ob+i] = bi[i];
}

// ---------------- pos-MLP hidden --------------------------------------------
__global__ __launch_bounds__(256) void pos_hidden_kernel(const float* __restrict__ pos,
                                                         const float* __restrict__ pw1){
    int b = blockIdx.y, n = blockIdx.x;
    __shared__ float prx[KNN], pry[KNN], prz[KNN];
    int t = threadIdx.x;
    const float* pb = pos + (size_t)b*3*NPTS;
    if (t < KNN){
        int m = g_idx[(b*NPTS+n)*KNN + t];
        prx[t] = pb[n]        - pb[m];
        pry[t] = pb[NPTS+n]   - pb[NPTS+m];
        prz[t] = pb[2*NPTS+n] - pb[2*NPTS+m];
    }
    __syncthreads();
    for (int e = t; e < KNN*PHID; e += 256){
        int k = e >> 6, hh = e & 63;
        float z = pw1[hh*3+0]*prx[k] + pw1[hh*3+1]*pry[k] + pw1[hh*3+2]*prz[k];
        z = z*g_sP[hh] + g_tP[hh];
        g_ph[((b*NPTS+n)*KNN + k)*PHID + hh] = rtf(fmaxf(z, 0.f));
    }
}

// ---------------- tf32 GEMM, cp.async 3-stage, conflict-free stride-20 smem --
// C[M][N] = A[M][K] * Bw[N][K]^T
// EPI 0: C = acc + bias[n]
// EPI 1: C = rtf(acc + bias[n])
// EPI 2: folded attn-hidden epilogue -> g_hid (rounded)
// EPI 3: C = acc
// EPI 4: fused softmax(k)+aggregate -> g_agg (rounded)
template<int EPI>
__global__ __launch_bounds__(256,2) void gemm2(const float* __restrict__ A,
        const float* __restrict__ Bw, float* __restrict__ C,
        int M, int N, int K, const float* __restrict__ bias,
        long strideAb, long strideCb){
    extern __shared__ __align__(16) float sm[];
    A += (long)blockIdx.z*strideAb;
    C += (long)blockIdx.z*strideCb;
    const int t = threadIdx.x, lane = t&31, w = t>>5;
    const int wm = w>>2, wn = w&3;
    const int m0 = blockIdx.x*128, n0 = blockIdx.y*128;
    const uint32_t smb = (uint32_t)__cvta_generic_to_shared(sm);
    float acc[4][4][4];
#pragma unroll
    for (int i=0;i<4;i++)
#pragma unroll
      for (int j=0;j<4;j++)
#pragma unroll
        for (int c=0;c<4;c++) acc[i][j][c] = 0.f;

    const int nIter = K >> 4;
    auto prefetch = [&](int st, int kt){
#pragma unroll
        for (int l=0;l<2;l++){
            int g = t + (l<<8);
            int row = g>>2, kq = (g&3)<<2;
            int arow = m0 + row; if (arow >= M) arow = M - 1;   // clamp: always in-bounds
            uint32_t d = smb + (uint32_t)((st*5120 + row*20 + kq)<<2);
            cp16(d, A + (long)arow*K + (kt<<4) + kq);
            uint32_t d2 = smb + (uint32_t)((st*5120 + 2560 + row*20 + kq)<<2);
            cp16(d2, Bw + (long)(n0+row)*K + (kt<<4) + kq);
        }
        cpcommit();
    };
    prefetch(0, 0);
    prefetch(1, 1);

    for (int it = 0; it < nIter; ++it){
        cpwait1();
        __syncthreads();
        if (it+2 < nIter) prefetch((it+2)%3, it+2);
        else cpcommit();
        const float* sA = sm + (it%3)*5120;
        const float* sB = sA + 2560;
#pragma unroll
        for (int k8=0;k8<2;k8++){
            int kb = k8*8 + (lane&3);
            uint32_t af[4][4]; uint32_t bf[4][2];
#pragma unroll
            for (int i=0;i<4;i++){
                const float* p = sA + (wm*64 + i*16 + (lane>>2))*20 + kb;
                af[i][0]=__float_as_uint(p[0]);
                af[i][1]=__float_as_uint(p[160]);
                af[i][2]=__float_as_uint(p[4]);
                af[i][3]=__float_as_uint(p[164]);
            }
#pragma unroll
            for (int j=0;j<4;j++){
                const float* p = sB + (wn*32 + j*8 + (lane>>2))*20 + kb;
                bf[j][0]=__float_as_uint(p[0]);
                bf[j][1]=__float_as_uint(p[4]);
            }
#pragma unroll
            for (int i=0;i<4;i++)
#pragma unroll
                for (int j=0;j<4;j++)
                    mma_tf32(acc[i][j][0],acc[i][j][1],acc[i][j][2],acc[i][j][3],
                             af[i][0],af[i][1],af[i][2],af[i][3], bf[j][0],bf[j][1]);
        }
        __syncthreads();
    }

    const int r0 = lane >> 2, cq = (lane & 3) << 1;
    if (EPI == 4){
#pragma unroll
        for (int i=0;i<4;i++){
            int mrow = m0 + wm*64 + i*16;
            if (mrow >= M) continue;
            int colidx = mrow >> 4;            // b*NP1 + nn
            int b  = colidx / NP1;
            int nn = colidx - b*NP1;
            long pebase = (nn > 0) ? (long)((b*NPTS + nn-1)*KNN)*DIM : 0;
            int kk0 = r0;                      // k for half 0; half 1 = kk0+8
#pragma unroll
            for (int j=0;j<4;j++){
                int c0 = n0 + wn*32 + j*8 + cq;
                float outv[2];
#pragma unroll
                for (int q=0;q<2;q++){
                    float l0 = acc[i][j][q], l1 = acc[i][j][2+q];
                    float mx = fmaxf(l0, l1);
                    mx = fmaxf(mx, __shfl_xor_sync(0xffffffffu, mx, 4));
                    mx = fmaxf(mx, __shfl_xor_sync(0xffffffffu, mx, 8));
                    mx = fmaxf(mx, __shfl_xor_sync(0xffffffffu, mx, 16));
                    float e0 = expf(l0 - mx), e1 = expf(l1 - mx);
                    float pv0 = 0.f, pv1 = 0.f;
                    if (nn > 0){
                        pv0 = g_pe[pebase + (long)kk0*DIM + c0 + q];
                        pv1 = g_pe[pebase + (long)(kk0+8)*DIM + c0 + q];
                    }
                    float s  = e0 + e1;
                    float ts = e0*pv0 + e1*pv1;
                    s  += __shfl_xor_sync(0xffffffffu, s, 4);
                    ts += __shfl_xor_sync(0xffffffffu, ts, 4);
                    s  += __shfl_xor_sync(0xffffffffu, s, 8);
                    ts += __shfl_xor_sync(0xffffffffu, ts, 8);
                    s  += __shfl_xor_sync(0xffffffffu, s, 16);
                    ts += __shfl_xor_sync(0xffffffffu, ts, 16);
                    float vv = g_v[(long)colidx*DIM + c0 + q];
                    outv[q] = rtf(vv + ts / s);
                }
                if (r0 == 0){
                    float2 o = make_float2(outv[0], outv[1]);
                    *(float2*)&g_agg[(long)colidx*DIM + c0] = o;
                }
            }
        }
        return;
    }
#pragma unroll
    for (int i=0;i<4;i++){
#pragma unroll
        for (int half=0; half<2; half++){
            int m = m0 + wm*64 + i*16 + r0 + half*8;
            if (m >= M) continue;
            if (EPI == 2){
                int b  = m >> 15;
                int n  = (m >> 4) & (NPTS-1);
                int kk = m & 15;
                int midx = g_idx[((b*NPTS)+n)*KNN + kk];
                const float* wq = g_w1q + (long)(b*NP1 + n + 1)*HID;
                const float* wk = g_w1k + (long)(b*NPTS + midx)*HID;
                float* dst = g_hid + (long)((b*NP1 + n + 1)*KNN + kk)*HID;
#pragma unroll
                for (int j=0;j<4;j++){
                    int h = n0 + wn*32 + j*8 + cq;
                    float2 q2 = *(const float2*)&wq[h];
                    float2 k2 = *(const float2*)&wk[h];
                    float2 p2 = *(const float2*)&g_w1pb[h];
                    float2 s2 = *(const float2*)&g_sA[h];
                    float2 t2 = *(const float2*)&g_tA[h];
                    float2 o;
                    o.x = rtf(fmaxf((acc[i][j][half*2+0] + q2.x - k2.x + p2.x)*s2.x + t2.x, 0.f));
                    o.y = rtf(fmaxf((acc[i][j][half*2+1] + q2.y - k2.y + p2.y)*s2.y + t2.y, 0.f));
                    *(float2*)&dst[h] = o;
                }
            } else {
                float* crow = C + (long)m*N;
#pragma unroll
                for (int j=0;j<4;j++){
                    int n = n0 + wn*32 + j*8 + cq;
                    float2 o;
                    if (EPI == 0){
                        float2 bv = *(const float2*)&bias[n];
                        o.x = acc[i][j][half*2+0] + bv.x;
                        o.y = acc[i][j][half*2+1] + bv.y;
                    } else if (EPI == 1){
                        float2 bv = *(const float2*)&bias[n];
                        o.x = rtf(acc[i][j][half*2+0] + bv.x);
                        o.y = rtf(acc[i][j][half*2+1] + bv.y);
                    } else {
                        o.x = acc[i][j][half*2+0];
                        o.y = acc[i][j][half*2+1];
                    }
                    *(float2*)&crow[n] = o;
                }
            }
        }
    }
}

// ---------------- cls hidden -------------------------------------------------
__global__ void cls_hidden_kernel(){
    int b = blockIdx.x >> 4, kk = blockIdx.x & 15;
    long col = (long)(b*NP1)*KNN + kk;
    for (int h = threadIdx.x; h < HID; h += 256){
        float v = rtf(fmaxf(g_w1q[(long)(b*NP1)*HID + h]*g_sA[h] + g_tA[h], 0.f));
        g_hid[col*HID + h] = v;
    }
}

// ---------------- finalize outputs ------------------------------------------
__global__ void finalize1_kernel(const float* __restrict__ x, float* __restrict__ out){
    int gid = blockIdx.x*256 + threadIdx.x;
    int n  = gid % NPTS;
    int ch = (gid / NPTS) % DIM;
    int b  = gid / (NPTS*DIM);
    out[gid] = g_y[((b*NP1) + (n+1))*DIM + ch] + x[gid];
}
__global__ void finalize2_kernel(float* __restrict__ out){
    int t = threadIdx.x;
    int b = t / DIM, ch = t % DIM;
    out[BB*DIM*NPTS + t] = g_y[(b*NP1)*DIM + ch];
}

// ---------------- launch -----------------------------------------------------
extern "C" void kernel_launch(void* const* d_in, const int* in_sizes, int n_in,
                              void* d_out, int out_size){
    const float* x        = (const float*)d_in[0];
    const float* pos      = (const float*)d_in[1];
    const float* W_start  = (const float*)d_in[2];
    const float* b_start  = (const float*)d_in[3];
    const float* W_key    = (const float*)d_in[4];
    const float* b_key    = (const float*)d_in[5];
    const float* W_query  = (const float*)d_in[6];
    const float* b_query  = (const float*)d_in[7];
    const float* W_value  = (const float*)d_in[8];
    const float* b_value  = (const float*)d_in[9];
    const float* pos_W1   = (const float*)d_in[10];
    const float* pos_b1   = (const float*)d_in[11];
    const float* pos_g    = (const float*)d_in[12];
    const float* pos_beta = (const float*)d_in[13];
    const float* pos_m    = (const float*)d_in[14];
    const float* pos_v    = (const float*)d_in[15];
    const float* pos_W2   = (const float*)d_in[16];
    const float* pos_b2   = (const float*)d_in[17];
    const float* attn_W1  = (const float*)d_in[18];
    const float* attn_b1  = (const float*)d_in[19];
    const float* attn_g   = (const float*)d_in[20];
    const float* attn_beta= (const float*)d_in[21];
    const float* attn_m   = (const float*)d_in[22];
    const float* attn_v   = (const float*)d_in[23];
    const float* attn_W2  = (const float*)d_in[24];
    const float* attn_b2  = (const float*)d_in[25];
    const float* W_end    = (const float*)d_in[26];
    const float* b_end    = (const float*)d_in[27];
    const float* pos_emb  = (const float*)d_in[28];
    const float* cls_tok  = (const float*)d_in[29];
    float* out = (float*)d_out;
    (void)attn_b2;

    float *pxT,*phx,*pq,*pk,*pv,*pph,*ppe,*phid,*pagg,*py,*pw1q,*pw1k,*pWc;
    float *prWs,*prWq,*prWk,*prWv,*prW1,*prP2,*prW2,*prWe;
    cudaGetSymbolAddress((void**)&pxT,  g_xT);
    cudaGetSymbolAddress((void**)&phx,  g_hx);
    cudaGetSymbolAddress((void**)&pq,   g_q);
    cudaGetSymbolAddress((void**)&pk,   g_k);
    cudaGetSymbolAddress((void**)&pv,   g_v);
    cudaGetSymbolAddress((void**)&pph,  g_ph);
    cudaGetSymbolAddress((void**)&ppe,  g_pe);
    cudaGetSymbolAddress((void**)&phid, g_hid);
    cudaGetSymbolAddress((void**)&pagg, g_agg);
    cudaGetSymbolAddress((void**)&py,   g_y);
    cudaGetSymbolAddress((void**)&pw1q, g_w1q);
    cudaGetSymbolAddress((void**)&pw1k, g_w1k);
    cudaGetSymbolAddress((void**)&pWc,  g_Wc);
    cudaGetSymbolAddress((void**)&prWs, g_rWs);
    cudaGetSymbolAddress((void**)&prWq, g_rWq);
    cudaGetSymbolAddress((void**)&prWk, g_rWk);
    cudaGetSymbolAddress((void**)&prWv, g_rWv);
    cudaGetSymbolAddress((void**)&prW1, g_rW1);
    cudaGetSymbolAddress((void**)&prP2, g_rP2);
    cudaGetSymbolAddress((void**)&prW2, g_rW2);
    cudaGetSymbolAddress((void**)&prWe, g_rWe);

    cudaFuncSetAttribute(gemm2<0>, cudaFuncAttributeMaxDynamicSharedMemorySize, GSMEM);
    cudaFuncSetAttribute(gemm2<1>, cudaFuncAttributeMaxDynamicSharedMemorySize, GSMEM);
    cudaFuncSetAttribute(gemm2<2>, cudaFuncAttributeMaxDynamicSharedMemorySize, GSMEM);
    cudaFuncSetAttribute(gemm2<3>, cudaFuncAttributeMaxDynamicSharedMemorySize, GSMEM);
    cudaFuncSetAttribute(gemm2<4>, cudaFuncAttributeMaxDynamicSharedMemorySize, GSMEM);

    // prep + weight rounding
    transpose_x_kernel<<<dim3(NPTS/32, INCH/32, BB), dim3(32,32)>>>(x);
    prep_kernel<<<1,1024>>>(attn_g, attn_beta, attn_m, attn_v, attn_b1,
                            pos_g, pos_beta, pos_m, pos_v, pos_b1,
                            attn_W1, pos_b2);
    wc_kernel<<<HID, PHID>>>(attn_W1, pos_W2);
    roundcpy_kernel<<<(DIM*INCH)/256,256>>>(W_start, prWs);
    roundcpy_kernel<<<(DIM*DIM)/256,256>>>(W_query, prWq);
    roundcpy_kernel<<<(DIM*DIM)/256,256>>>(W_key,   prWk);
    roundcpy_kernel<<<(DIM*DIM)/256,256>>>(W_value, prWv);
    roundcpy_kernel<<<(HID*DIM)/256,256>>>(attn_W1, prW1);
    roundcpy_kernel<<<(DIM*PHID)/256,256>>>(pos_W2, prP2);
    roundcpy_kernel<<<(DIM*HID)/256,256>>>(attn_W2, prW2);
    roundcpy_kernel<<<(INCH*DIM)/256,256>>>(W_end,  prWe);
    init_cls_kernel<<<BB, DIM>>>(cls_tok);
    knn_part_kernel<<<dim3(NPTS/256, BB, NCH), 256>>>(pos);
    knn_merge_kernel<<<dim3(NPTS/256, BB), 256>>>();

    // hx[1:] = W_start @ x + b
    gemm2<1><<<dim3(NPTS/128, DIM/128, BB), 256, GSMEM>>>(
        pxT, prWs, phx + DIM, NPTS, DIM, INCH, b_start,
        (long)NPTS*INCH, (long)NP1*DIM);

    // q,k,v
    gemm2<1><<<dim3((BB*NP1+127)/128, DIM/128, 1), 256, GSMEM>>>(
        phx, prWq, pq, BB*NP1, DIM, DIM, b_query, 0, 0);
    gemm2<1><<<dim3((BB*NP1+127)/128, DIM/128, 1), 256, GSMEM>>>(
        phx, prWk, pk, BB*NP1, DIM, DIM, b_key, 0, 0);
    gemm2<0><<<dim3((BB*NP1+127)/128, DIM/128, 1), 256, GSMEM>>>(
        phx, prWv, pv, BB*NP1, DIM, DIM, b_value, 0, 0);

    addpos_kernel<<<BB, DIM>>>(pos_emb);

    // w1q (all rows, cls row includes pos_emb), w1k (rows 1..)
    gemm2<3><<<dim3((BB*NP1+127)/128, HID/128, 1), 256, GSMEM>>>(
        pq, prW1, pw1q, BB*NP1, HID, DIM, nullptr, 0, 0);
    gemm2<3><<<dim3(NPTS/128, HID/128, BB), 256, GSMEM>>>(
        pk + DIM, prW1, pw1k, NPTS, HID, DIM, nullptr,
        (long)NP1*DIM, (long)NPTS*HID);

    // pos-MLP
    pos_hidden_kernel<<<dim3(NPTS, BB), 256>>>(pos, pos_W1);
    gemm2<0><<<dim3(NK/128, DIM/128, 1), 256, GSMEM>>>(
        pph, prP2, ppe, NK, DIM, PHID, pos_b2, 0, 0);

    // folded attn hidden
    gemm2<2><<<dim3(NK/128, HID/128, 1), 256, GSMEM>>>(
        pph, pWc, nullptr, NK, HID, PHID, nullptr, 0, 0);
    cls_hidden_kernel<<<BB*KNN, 256>>>();

    // logits + fused softmax/aggregate -> g_agg
    gemm2<4><<<dim3((NCOL+127)/128, DIM/128, 1), 256, GSMEM>>>(
        phid, prW2, nullptr, NCOL, DIM, HID, nullptr, 0, 0);

    // y = W_end @ agg + b
    gemm2<0><<<dim3((BB*NP1+127)/128, DIM/128, 1), 256, GSMEM>>>(
        pagg, prWe, py, BB*NP1, DIM, DIM, b_end, 0, 0);

    finalize1_kernel<<<(BB*DIM*NPTS)/256, 256>>>(x, out);
    finalize2_kernel<<<1, BB*DIM>>>(out);
}